// round 16
// baseline (speedup 1.0000x reference)
#include <cuda_runtime.h>
#include <cuda_bf16.h>
#include <math.h>
#include <stdint.h>

#define NATC 1024
#define DEGC 32
#define DC   128
#define RC   64
#define LC   3
#define BC   16
#define EC   (NATC*DEGC)      /* 32768 */
#define HDC  (DC/2)           /* 64 */
#define BNAT (BC*1024)        /* 16384 */
#define BE   ((size_t)BC*EC)  /* 524288 */
#define M4   (4*BNAT)         /* 65536 */
#define NQ   1024
#define QB   16
#define DMAXF 20.0f
#define LOG2C 0.69314718055994530942f

// ---------------- scratch (allocation-free: __device__ globals) ----------------
__device__ float g_xw4 [(size_t)4*BNAT*DC];
__device__ float g_feat4[(size_t)4*BNAT*DC];
__device__ float g_h4  [(size_t)4*BNAT*HDC];
__device__ float g_sigB[(size_t)BNAT*DC];
__device__ float g_d   [BE];
__device__ float g_ddot[(size_t)BE*3];
__device__ float          g_tabF [(size_t)NQ*DC];
__device__ __nv_bfloat16  g_tabDh[(size_t)NQ*DC];
__device__ float          g_tabDf[(size_t)NQ*DC];
__device__ int   g_sflag[EC];
// bf16 hi/lo operand planes (producer-packed)
__device__ __nv_bfloat16 g_feah[(size_t)4*BNAT*DC], g_feal[(size_t)4*BNAT*DC];
__device__ __nv_bfloat16 g_y4h [(size_t)4*BNAT*DC], g_y4l [(size_t)4*BNAT*DC];
__device__ __nv_bfloat16 g_t3h [(size_t)4*BNAT*DC], g_t3l [(size_t)4*BNAT*DC];
// pre-split transposed weights: [slot][n][k], slot = l*3 + {W1,W2,W3}; Wd separate
__device__ __nv_bfloat16 g_WH[(size_t)9*DC*DC], g_WL[(size_t)9*DC*DC];
__device__ __nv_bfloat16 g_WdH[(size_t)HDC*DC], g_WdL[(size_t)HDC*DC];

// ---------------- math helpers ----------------
__device__ __forceinline__ float sspf(float x) {
    return fmaxf(x, 0.f) + log1pf(expf(-fabsf(x))) - LOG2C;
}
__device__ __forceinline__ float sigf(float x) {
    return 1.f / (1.f + expf(-x));
}
__device__ __forceinline__ uint32_t smem_u32(const void* p) {
    uint32_t a;
    asm("{ .reg .u64 t; cvta.to.shared.u64 t, %1; cvt.u32.u64 %0, t; }" : "=r"(a) : "l"(p));
    return a;
}
__device__ __forceinline__ uint32_t pack_hi(float x0, float x1) {
    __nv_bfloat162 v; v.x = __float2bfloat16(x0); v.y = __float2bfloat16(x1);
    return *reinterpret_cast<uint32_t*>(&v);
}
__device__ __forceinline__ uint32_t pack_lo(float x0, float x1) {
    __nv_bfloat16 h0 = __float2bfloat16(x0), h1 = __float2bfloat16(x1);
    __nv_bfloat162 v;
    v.x = __float2bfloat16(x0 - __bfloat162float(h0));
    v.y = __float2bfloat16(x1 - __bfloat162float(h1));
    return *reinterpret_cast<uint32_t*>(&v);
}

// ---------------- prep ----------------
__global__ void prepBuildK(const int* __restrict__ idx_i, const int* __restrict__ idx_j) {
    int e = blockIdx.x * blockDim.x + threadIdx.x;
    if (e >= EC) return;
    g_sflag[e] = (idx_i[e] == 0 || idx_j[e] == 0) ? 1 : 0;
}

__global__ void initK(const float* __restrict__ emb, const int* __restrict__ types) {
    int gid = blockIdx.x * blockDim.x + threadIdx.x;
    if (gid >= BNAT * DC) return;
    int bn = gid / DC;
    int d  = gid - bn * DC;
    int ty = types[bn];
    const size_t TB = (size_t)BNAT * DC;
    float v = emb[(size_t)ty * DC + d];
    g_feat4[gid]        = v;
    g_feat4[TB + gid]   = 0.f;
    g_feat4[2*TB + gid] = 0.f;
    g_feat4[3*TB + gid] = 0.f;
    __nv_bfloat16 h = __float2bfloat16(v);
    __nv_bfloat16 l = __float2bfloat16(v - __bfloat162float(h));
    __nv_bfloat16 z = __float2bfloat16(0.f);
    g_feah[gid] = h; g_feal[gid] = l;
    g_feah[TB+gid] = z; g_feal[TB+gid] = z;
    g_feah[2*TB+gid] = z; g_feal[2*TB+gid] = z;
    g_feah[3*TB+gid] = z; g_feal[3*TB+gid] = z;
}

__global__ void distK(const float* __restrict__ pos,
                      const int* __restrict__ idx_i, const int* __restrict__ idx_j) {
    int gid = blockIdx.x * blockDim.x + threadIdx.x;
    if (gid >= (int)BE) return;
    int b = gid / EC, e = gid - b * EC;
    int i = idx_i[e], j = idx_j[e];
    const float* pi = pos + ((size_t)b * NATC + i) * 3;
    const float* pj = pos + ((size_t)b * NATC + j) * 3;
    float dx = pi[0]-pj[0], dy = pi[1]-pj[1], dz = pi[2]-pj[2];
    float dv = sqrtf(dx*dx + dy*dy + dz*dz + 1e-8f);
    g_d[gid] = dv;
    float c = (float)((i == 0) - (j == 0));
    float inv = c / dv;
    g_ddot[(size_t)gid*3 + 0] = dx * inv;
    g_ddot[(size_t)gid*3 + 1] = dy * inv;
    g_ddot[(size_t)gid*3 + 2] = dz * inv;
}

// ---------------- pre-split all weights (transposed [n][k], bf16 hi/lo), 4 chunks/matrix ----
__global__ void packWK(const float* __restrict__ W1, const float* __restrict__ W2,
                       const float* __restrict__ W3, const float* __restrict__ Wd) {
    int bid = blockIdx.x, tid = threadIdx.x;
    int mat = bid >> 2, part = bid & 3;
    if (mat < 9) {
        int l = mat / 3, w = mat % 3;
        const float* src = (w == 0 ? W1 : (w == 1 ? W2 : W3)) + (size_t)l*DC*DC;
        __nv_bfloat16* dh = g_WH + (size_t)mat*DC*DC;
        __nv_bfloat16* dl = g_WL + (size_t)mat*DC*DC;
        int n0 = part * (DC*DC/4), n1 = n0 + DC*DC/4;
        for (int i = n0 + tid; i < n1; i += 256) {
            int n = i >> 7, k = i & 127;
            float x = src[(size_t)k*DC + n];
            __nv_bfloat16 h = __float2bfloat16(x);
            dh[i] = h;
            dl[i] = __float2bfloat16(x - __bfloat162float(h));
        }
    } else {
        int n0 = part * (HDC*DC/4), n1 = n0 + HDC*DC/4;
        for (int i = n0 + tid; i < n1; i += 256) {
            int n = i >> 7, k = i & 127;
            float x = Wd[(size_t)k*HDC + n];
            __nv_bfloat16 h = __float2bfloat16(x);
            g_WdH[i] = h;
            g_WdL[i] = __float2bfloat16(x - __bfloat162float(h));
        }
    }
}

// ------ per-layer edge-MLP lookup table (weights cached in dynamic smem) ------
__global__ void tabK2(const float* __restrict__ Wf1, const float* __restrict__ bf1,
                      const float* __restrict__ Wf2, const float* __restrict__ bf2,
                      const float* __restrict__ centers, const float* __restrict__ gammaA, int l) {
    extern __shared__ float sw[];
    float* w1s = sw;
    float* w2s = sw + RC*DC;
    __shared__ float rbf[RC], drb[RC], s1[DC], ds1[DC];
    int t = threadIdx.x;
    for (int idx = t; idx < RC*DC; idx += DC) w1s[idx] = Wf1[(size_t)l*RC*DC + idx];
    for (int idx = t; idx < DC*DC; idx += DC) w2s[idx] = Wf2[(size_t)l*DC*DC + idx];
    float b1v = bf1[l*DC + t];
    float b2v = bf2[l*DC + t];
    float gm = 0.f, cc = 0.f;
    if (t < RC) { gm = gammaA[l*RC + t]; cc = centers[l*RC + t]; }
    __syncthreads();

    const float hh = DMAXF / (float)(NQ - 1);
    for (int qi = 0; qi < QB; qi++) {
        int q = blockIdx.x * QB + qi;
        float dq = q * hh;
        if (t < RC) {
            float diff = dq - cc;
            float r = expf(-gm * diff * diff);
            rbf[t] = r;
            drb[t] = -2.f * gm * diff * r;
        }
        __syncthreads();
        float t1 = b1v, dt1 = 0.f;
        #pragma unroll 8
        for (int r = 0; r < RC; r++) {
            float w = w1s[r * DC + t];
            t1  += rbf[r] * w;
            dt1 += drb[r] * w;
        }
        s1[t]  = sspf(t1);
        ds1[t] = sigf(t1) * dt1;
        __syncthreads();
        float t2 = b2v, dt2 = 0.f;
        #pragma unroll 8
        for (int k = 0; k < DC; k++) {
            float w = w2s[k * DC + t];
            t2  += s1[k] * w;
            dt2 += ds1[k] * w;
        }
        float fval = sspf(t2);
        float fder = sigf(t2) * dt2;
        g_tabF [(size_t)q*DC + t] = fval;
        g_tabDh[(size_t)q*DC + t] = __float2bfloat16(hh * fder);
        g_tabDf[(size_t)q*DC + t] = fder;
        __syncthreads();
    }
}

// ---------------- GEMM helpers ----------------
#define PADK 136
#define BPL (128 * PADK * 2)      /* 34816 B: one 128-row bf16 plane */

__device__ __forceinline__ void mma16816(float* c, uint32_t a0, uint32_t a1, uint32_t a2, uint32_t a3,
                                         uint32_t b0, uint32_t b1) {
    asm volatile(
        "mma.sync.aligned.m16n8k16.row.col.f32.bf16.bf16.f32 "
        "{%0,%1,%2,%3}, {%4,%5,%6,%7}, {%8,%9}, {%0,%1,%2,%3};"
        : "+f"(c[0]), "+f"(c[1]), "+f"(c[2]), "+f"(c[3])
        : "r"(a0), "r"(a1), "r"(a2), "r"(a3), "r"(b0), "r"(b1));
}
#define LDSM4(r0, r1, r2, r3, addr) \
    asm volatile("ldmatrix.sync.aligned.m8n8.x4.shared.b16 {%0,%1,%2,%3}, [%4];" \
        : "=r"(r0), "=r"(r1), "=r"(r2), "=r"(r3) : "r"(addr))
#define CP16(sa, ga) \
    asm volatile("cp.async.cg.shared.global [%0], [%1], 16;" :: "r"(sa), "l"(ga))
#define CPCOMMIT() asm volatile("cp.async.commit_group;" ::: "memory")
#define CPWAIT(n)  asm volatile("cp.async.wait_group %0;" :: "n"(n) : "memory")

// ---------------- persistent GEMM, cp.async double-buffered A tiles ----------------
// MODE 0: standard (bias rows<biasRows, +res, fp32 C, optional Chg/Clg bf16 copy)
// MODE 1: primal W2: t3 = acc + bias; write sig(t3) to g_sigB, ssp(t3) to Chg/Clg
// MODE 2: tangent W2: val = acc * g_sigB[r & (BNAT-1)]; write to Chg/Clg
template<int NN, int MODE>
__global__ void __launch_bounds__(256) mmaGemmPS(
    const __nv_bfloat16* __restrict__ Ahg, const __nv_bfloat16* __restrict__ Alg,
    const __nv_bfloat16* __restrict__ Whg, const __nv_bfloat16* __restrict__ Wlg,
    float* __restrict__ C, int M,
    const float* __restrict__ bias, int biasRows, const float* __restrict__ res,
    __nv_bfloat16* __restrict__ Chg, __nv_bfloat16* __restrict__ Clg)
{
    extern __shared__ char sm[];
    const int tid = threadIdx.x;
    const int nT = M >> 7;
    if (blockIdx.x >= nT) return;
    constexpr uint32_t WBYTES = (uint32_t)NN * PADK * 2;
    const uint32_t smemU = smem_u32(sm);
    const uint32_t aBase = 2u * WBYTES;

    {
        #pragma unroll
        for (int it = 0; it < NN*16/256; it++) {
            int idx = it * 256 + tid;
            int n = idx >> 4, kq = idx & 15;
            uint32_t off = (uint32_t)n * (PADK*2) + kq * 16;
            CP16(smemU + off,           (const char*)Whg + idx*16);
            CP16(smemU + WBYTES + off,  (const char*)Wlg + idx*16);
        }
    }
    {
        int t0 = blockIdx.x;
        #pragma unroll
        for (int it = 0; it < 8; it++) {
            int idx = it * 256 + tid;
            int row = idx >> 4, kq = idx & 15;
            uint32_t off = aBase + (uint32_t)row * (PADK*2) + kq * 16;
            CP16(smemU + off,       (const char*)(Ahg + ((size_t)t0*128 + row) * DC) + kq*16);
            CP16(smemU + BPL + off, (const char*)(Alg + ((size_t)t0*128 + row) * DC) + kq*16);
        }
    }
    CPCOMMIT();

    const int wid = tid >> 5, lane = tid & 31;
    const int wm = wid & 3, wn = wid >> 2;
    const int g0 = (lane >> 3) & 1, g1 = (lane >> 4) & 1, r8 = lane & 7;
    const int lr = lane >> 2, lc = lane & 3;
    constexpr int NT = NN / 16;

    const uint32_t aOff = 2u * ((uint32_t)(wm*32 + g0*8 + r8) * PADK + g1*8);
    const uint32_t bAddr0 = smemU + 2u * ((uint32_t)(wn*(NN/2) + g1*8 + r8) * PADK + g0*8);

    int cb = 0;
    for (int t = blockIdx.x; t < nT; t += gridDim.x) {
        const int tn = t + gridDim.x;
        const bool more = tn < nT;
        if (more) {
            uint32_t nb = aBase + (uint32_t)(cb ^ 1) * (2*BPL);
            #pragma unroll
            for (int it = 0; it < 8; it++) {
                int idx = it * 256 + tid;
                int row = idx >> 4, kq = idx & 15;
                uint32_t off = nb + (uint32_t)row * (PADK*2) + kq * 16;
                CP16(smemU + off,       (const char*)(Ahg + ((size_t)tn*128 + row) * DC) + kq*16);
                CP16(smemU + BPL + off, (const char*)(Alg + ((size_t)tn*128 + row) * DC) + kq*16);
            }
            CPCOMMIT();
            CPWAIT(1);
        } else {
            CPWAIT(0);
        }
        __syncthreads();

        float acc[2][NT][4];
        #pragma unroll
        for (int mt = 0; mt < 2; mt++)
            #pragma unroll
            for (int nt = 0; nt < NT; nt++)
                #pragma unroll
                for (int q = 0; q < 4; q++) acc[mt][nt][q] = 0.f;

        const uint32_t aAddr0 = smemU + aBase + (uint32_t)cb * (2*BPL) + aOff;
        #pragma unroll
        for (int pass = 0; pass < 3; pass++) {
            const uint32_t aP = aAddr0 + ((pass == 1) ? (uint32_t)BPL : 0u);
            const uint32_t bP = bAddr0 + ((pass == 2) ? WBYTES : 0u);
            #pragma unroll
            for (int ks = 0; ks < 8; ks++) {
                uint32_t a[8];
                LDSM4(a[0], a[1], a[2], a[3], aP + ks*32);
                LDSM4(a[4], a[5], a[6], a[7], aP + 16u*2u*PADK + ks*32);
                #pragma unroll
                for (int p = 0; p < NT/2; p++) {
                    uint32_t bfr[4];
                    LDSM4(bfr[0], bfr[1], bfr[2], bfr[3], bP + (uint32_t)(p*16*2*PADK) + ks*32);
                    mma16816(acc[0][2*p],   a[0], a[1], a[2], a[3], bfr[0], bfr[1]);
                    mma16816(acc[1][2*p],   a[4], a[5], a[6], a[7], bfr[0], bfr[1]);
                    mma16816(acc[0][2*p+1], a[0], a[1], a[2], a[3], bfr[2], bfr[3]);
                    mma16816(acc[1][2*p+1], a[4], a[5], a[6], a[7], bfr[2], bfr[3]);
                }
            }
        }
        __syncthreads();

        const int m0 = t * 128;
        const int arow0 = wm * 32 + lr;
        #pragma unroll
        for (int mt = 0; mt < 2; mt++) {
            int r0 = m0 + arow0 + mt * 16;
            int r1 = r0 + 8;
            #pragma unroll
            for (int nt = 0; nt < NT; nt++) {
                int col = wn * (NN/2) + nt * 8 + lc * 2;
                float2 v0 = make_float2(acc[mt][nt][0], acc[mt][nt][1]);
                float2 v1 = make_float2(acc[mt][nt][2], acc[mt][nt][3]);
                if (MODE == 0) {
                    bool ub0 = (bias != nullptr) && (r0 < biasRows);
                    bool ub1 = (bias != nullptr) && (r1 < biasRows);
                    if (ub0) { v0.x += bias[col]; v0.y += bias[col+1]; }
                    if (ub1) { v1.x += bias[col]; v1.y += bias[col+1]; }
                    if (res) {
                        float2 r0v = *reinterpret_cast<const float2*>(res + (size_t)r0 * NN + col);
                        float2 r1v = *reinterpret_cast<const float2*>(res + (size_t)r1 * NN + col);
                        v0.x += r0v.x; v0.y += r0v.y;
                        v1.x += r1v.x; v1.y += r1v.y;
                    }
                    *reinterpret_cast<float2*>(C + (size_t)r0 * NN + col) = v0;
                    *reinterpret_cast<float2*>(C + (size_t)r1 * NN + col) = v1;
                    if (Chg) {
                        *reinterpret_cast<uint32_t*>(Chg + (size_t)r0 * NN + col) = pack_hi(v0.x, v0.y);
                        *reinterpret_cast<uint32_t*>(Clg + (size_t)r0 * NN + col) = pack_lo(v0.x, v0.y);
                        *reinterpret_cast<uint32_t*>(Chg + (size_t)r1 * NN + col) = pack_hi(v1.x, v1.y);
                        *reinterpret_cast<uint32_t*>(Clg + (size_t)r1 * NN + col) = pack_lo(v1.x, v1.y);
                    }
                } else if (MODE == 1) {
                    v0.x += bias[col]; v0.y += bias[col+1];
                    v1.x += bias[col]; v1.y += bias[col+1];
                    float2 s0 = make_float2(sigf(v0.x), sigf(v0.y));
                    float2 s1 = make_float2(sigf(v1.x), sigf(v1.y));
                    *reinterpret_cast<float2*>(g_sigB + (size_t)r0 * NN + col) = s0;
                    *reinterpret_cast<float2*>(g_sigB + (size_t)r1 * NN + col) = s1;
                    v0.x = sspf(v0.x); v0.y = sspf(v0.y);
                    v1.x = sspf(v1.x); v1.y = sspf(v1.y);
                    *reinterpret_cast<uint32_t*>(Chg + (size_t)r0 * NN + col) = pack_hi(v0.x, v0.y);
                    *reinterpret_cast<uint32_t*>(Clg + (size_t)r0 * NN + col) = pack_lo(v0.x, v0.y);
                    *reinterpret_cast<uint32_t*>(Chg + (size_t)r1 * NN + col) = pack_hi(v1.x, v1.y);
                    *reinterpret_cast<uint32_t*>(Clg + (size_t)r1 * NN + col) = pack_lo(v1.x, v1.y);
                } else {  // MODE 2
                    float2 s0 = *reinterpret_cast<const float2*>(g_sigB + (size_t)(r0 & (BNAT-1)) * NN + col);
                    float2 s1 = *reinterpret_cast<const float2*>(g_sigB + (size_t)(r1 & (BNAT-1)) * NN + col);
                    v0.x *= s0.x; v0.y *= s0.y;
                    v1.x *= s1.x; v1.y *= s1.y;
                    *reinterpret_cast<uint32_t*>(Chg + (size_t)r0 * NN + col) = pack_hi(v0.x, v0.y);
                    *reinterpret_cast<uint32_t*>(Clg + (size_t)r0 * NN + col) = pack_lo(v0.x, v0.y);
                    *reinterpret_cast<uint32_t*>(Chg + (size_t)r1 * NN + col) = pack_hi(v1.x, v1.y);
                    *reinterpret_cast<uint32_t*>(Clg + (size_t)r1 * NN + col) = pack_lo(v1.x, v1.y);
                }
            }
        }
        cb ^= 1;
    }
}

// -------- vectorized agg: warp = atom, lane = 4 cols; writes bf16 hi/lo y4 --------
template<bool LIGHT>
__global__ void __launch_bounds__(128) aggV(const int* __restrict__ idx_j) {
    const int b = blockIdx.y;
    const int warp = threadIdx.x >> 5, lane = threadIdx.x & 31;
    const int i = blockIdx.x * 4 + warp;
    const size_t TBq = ((size_t)BNAT * DC) >> 2;
    const float invh = (float)(NQ - 1) / DMAXF;

    __shared__ float sd[128], sdx[128], sdy[128], sdz[128];
    __shared__ int sj[128], sf[128];
    {
        int tid = threadIdx.x;
        int e = blockIdx.x * 128 + tid;
        sd[tid] = g_d[(size_t)b*EC + e];
        sj[tid] = idx_j[e];
        sf[tid] = g_sflag[e];
        size_t db = ((size_t)b*EC + e) * 3;
        sdx[tid] = g_ddot[db + 0];
        sdy[tid] = g_ddot[db + 1];
        sdz[tid] = g_ddot[db + 2];
    }
    __syncthreads();

    const float4* xp = reinterpret_cast<const float4*>(g_xw4);
    const float4* tF = reinterpret_cast<const float4*>(g_tabF);
    const float4* tD = reinterpret_cast<const float4*>(g_tabDf);
    const uint2*  tH = reinterpret_cast<const uint2*>(g_tabDh);

    float4 y  = make_float4(0.f,0.f,0.f,0.f);
    float4 ya = y, yb_ = y, yc = y;
    const int e0 = warp * 32;

    #pragma unroll 4
    for (int eo = 0; eo < DEGC; eo++) {
        int ee = e0 + eo;
        float dv = sd[ee];
        float u = fminf(dv * invh, (float)(NQ - 1));
        int q = (int)u;
        if (q > NQ - 2) q = NQ - 2;
        float w = u - (float)q;
        float w2 = w*w, w3 = w2*w;
        float h00 = 2.f*w3 - 3.f*w2 + 1.f;
        float h01 = 1.f - h00;
        float h10 = w3 - 2.f*w2 + w;
        float h11 = w3 - w2;

        int ti0 = q * 32 + lane, ti1 = ti0 + 32;
        float4 f0 = tF[ti0], f1 = tF[ti1];
        uint2 hu0 = tH[ti0], hu1 = tH[ti1];
        float2 d0lo = __bfloat1622float2(*reinterpret_cast<const __nv_bfloat162*>(&hu0.x));
        float2 d0hi = __bfloat1622float2(*reinterpret_cast<const __nv_bfloat162*>(&hu0.y));
        float2 d1lo = __bfloat1622float2(*reinterpret_cast<const __nv_bfloat162*>(&hu1.x));
        float2 d1hi = __bfloat1622float2(*reinterpret_cast<const __nv_bfloat162*>(&hu1.y));

        float4 fv;
        fv.x = h00*f0.x + h01*f1.x + h10*d0lo.x + h11*d1lo.x;
        fv.y = h00*f0.y + h01*f1.y + h10*d0lo.y + h11*d1lo.y;
        fv.z = h00*f0.z + h01*f1.z + h10*d0hi.x + h11*d1hi.x;
        fv.w = h00*f0.w + h01*f1.w + h10*d0hi.y + h11*d1hi.y;

        int j = sj[ee];
        size_t xb = (((size_t)b*NATC + j) << 5) + lane;
        float4 xv = xp[xb];
        y.x += xv.x*fv.x; y.y += xv.y*fv.y; y.z += xv.z*fv.z; y.w += xv.w*fv.w;
        if (!LIGHT) {
            float4 x0 = xp[TBq + xb];
            float4 x1 = xp[2*TBq + xb];
            float4 x2 = xp[3*TBq + xb];
            ya.x += x0.x*fv.x; ya.y += x0.y*fv.y; ya.z += x0.z*fv.z; ya.w += x0.w*fv.w;
            yb_.x += x1.x*fv.x; yb_.y += x1.y*fv.y; yb_.z += x1.z*fv.z; yb_.w += x1.w*fv.w;
            yc.x += x2.x*fv.x; yc.y += x2.y*fv.y; yc.z += x2.z*fv.z; yc.w += x2.w*fv.w;
        }

        if (sf[ee]) {
            float4 g0v = tD[ti0], g1v = tD[ti1];
            float dcom = 6.f * (w2 - w) * invh;
            float c0 = 3.f*w2 - 4.f*w + 1.f;
            float c1 = 3.f*w2 - 2.f*w;
            float4 F;
            F.x = dcom*(f0.x - f1.x) + c0*g0v.x + c1*g1v.x;
            F.y = dcom*(f0.y - f1.y) + c0*g0v.y + c1*g1v.y;
            F.z = dcom*(f0.z - f1.z) + c0*g0v.z + c1*g1v.z;
            F.w = dcom*(f0.w - f1.w) + c0*g0v.w + c1*g1v.w;
            float ax = sdx[ee], ay = sdy[ee], az = sdz[ee];
            float4 xF;
            xF.x = xv.x*F.x; xF.y = xv.y*F.y; xF.z = xv.z*F.z; xF.w = xv.w*F.w;
            ya.x += ax*xF.x; ya.y += ax*xF.y; ya.z += ax*xF.z; ya.w += ax*xF.w;
            yb_.x += ay*xF.x; yb_.y += ay*xF.y; yb_.z += ay*xF.z; yb_.w += ay*xF.w;
            yc.x += az*xF.x; yc.y += az*xF.y; yc.z += az*xF.z; yc.w += az*xF.w;
        }
    }

    size_t bn = (size_t)b*NATC + i;
    int co = lane * 4;
    #pragma unroll
    for (int c = 0; c < 4; c++) {
        float4 v = (c == 0) ? y : (c == 1) ? ya : (c == 2) ? yb_ : yc;
        size_t base = (bn + (size_t)c * BNAT) * DC + co;
        *reinterpret_cast<uint2*>(g_y4h + base) = make_uint2(pack_hi(v.x, v.y), pack_hi(v.z, v.w));
        *reinterpret_cast<uint2*>(g_y4l + base) = make_uint2(pack_lo(v.x, v.y), pack_lo(v.z, v.w));
    }
}

// ---------------- final energy tangent reduction ----------------
__global__ void energyK(const float* __restrict__ We, float* __restrict__ out) {
    int b = blockIdx.x, tid = threadIdx.x;
    const size_t TH = (size_t)BNAT * HDC;
    float a0 = 0.f, a1 = 0.f, a2 = 0.f;
    for (int idx = tid; idx < NATC * HDC; idx += 256) {
        int k = idx & (HDC - 1);
        size_t base = (size_t)b * NATC * HDC + idx;
        float p = g_h4[base];
        float w = We[k] * sigf(p);
        a0 += w * g_h4[TH   + base];
        a1 += w * g_h4[2*TH + base];
        a2 += w * g_h4[3*TH + base];
    }
    __shared__ float r0[256], r1[256], r2[256];
    r0[tid] = a0; r1[tid] = a1; r2[tid] = a2;
    __syncthreads();
    for (int s = 128; s > 0; s >>= 1) {
        if (tid < s) { r0[tid] += r0[tid+s]; r1[tid] += r1[tid+s]; r2[tid] += r2[tid+s]; }
        __syncthreads();
    }
    if (tid == 0) {
        out[b*3 + 0] = -r0[0];
        out[b*3 + 1] = -r1[0];
        out[b*3 + 2] = -r2[0];
    }
}

// ---------------- host ----------------
extern "C" void kernel_launch(void* const* d_in, const int* in_sizes, int n_in,
                              void* d_out, int out_size) {
    const float* pos     = (const float*)d_in[0];
    const int*   types   = (const int*)  d_in[1];
    const int*   idx_i   = (const int*)  d_in[2];
    const int*   idx_j   = (const int*)  d_in[3];
    /* d_in[4] = seg_i (== idx_i, unused) */
    const float* emb     = (const float*)d_in[5];
    const float* W1      = (const float*)d_in[6];
    const float* b1      = (const float*)d_in[7];
    const float* Wf1     = (const float*)d_in[8];
    const float* bf1     = (const float*)d_in[9];
    const float* Wf2     = (const float*)d_in[10];
    const float* bf2     = (const float*)d_in[11];
    const float* W2      = (const float*)d_in[12];
    const float* b2      = (const float*)d_in[13];
    const float* W3      = (const float*)d_in[14];
    const float* b3      = (const float*)d_in[15];
    const float* centers = (const float*)d_in[16];
    const float* gammaA  = (const float*)d_in[17];
    const float* Wd      = (const float*)d_in[18];
    const float* bd      = (const float*)d_in[19];
    const float* We      = (const float*)d_in[20];
    float* out = (float*)d_out;

    float *feat4, *xw4, *h4;
    __nv_bfloat16 *feah, *feal, *y4h, *y4l, *t3h, *t3l, *WH, *WL, *WdH, *WdL;
    cudaGetSymbolAddress((void**)&feat4, g_feat4);
    cudaGetSymbolAddress((void**)&xw4,  g_xw4);
    cudaGetSymbolAddress((void**)&h4,   g_h4);
    cudaGetSymbolAddress((void**)&feah, g_feah);
    cudaGetSymbolAddress((void**)&feal, g_feal);
    cudaGetSymbolAddress((void**)&y4h,  g_y4h);
    cudaGetSymbolAddress((void**)&y4l,  g_y4l);
    cudaGetSymbolAddress((void**)&t3h,  g_t3h);
    cudaGetSymbolAddress((void**)&t3l,  g_t3l);
    cudaGetSymbolAddress((void**)&WH,   g_WH);
    cudaGetSymbolAddress((void**)&WL,   g_WL);
    cudaGetSymbolAddress((void**)&WdH,  g_WdH);
    cudaGetSymbolAddress((void**)&WdL,  g_WdL);

    const int tabSmem = (RC*DC + DC*DC) * sizeof(float);               // 96 KB
    const int psSmem128 = 2*(128*PADK*2) + 4*BPL;                      // 204 KB
    const int psSmem64  = 2*(64*PADK*2)  + 4*BPL;                      // 170 KB
    cudaFuncSetAttribute(tabK2, cudaFuncAttributeMaxDynamicSharedMemorySize, tabSmem);
    cudaFuncSetAttribute(mmaGemmPS<128,0>, cudaFuncAttributeMaxDynamicSharedMemorySize, psSmem128);
    cudaFuncSetAttribute(mmaGemmPS<128,1>, cudaFuncAttributeMaxDynamicSharedMemorySize, psSmem128);
    cudaFuncSetAttribute(mmaGemmPS<128,2>, cudaFuncAttributeMaxDynamicSharedMemorySize, psSmem128);
    cudaFuncSetAttribute(mmaGemmPS<64,0>,  cudaFuncAttributeMaxDynamicSharedMemorySize, psSmem64);

    prepBuildK<<<EC/256, 256>>>(idx_i, idx_j);
    initK<<<(BNAT*DC)/256, 256>>>(emb, types);
    distK<<<(int)(BE/256), 256>>>(pos, idx_i, idx_j);
    packWK<<<40, 256>>>(W1, W2, W3, Wd);

    const int gBig = 152 < M4/128 ? 152 : M4/128;
    const int gSm  = 152 < BNAT/128 ? 152 : BNAT/128;
    const int gT   = 152 < (3*BNAT)/128 ? 152 : (3*BNAT)/128;
    const size_t TB = (size_t)BNAT * DC;

    for (int l = 0; l < LC; l++) {
        int mW1 = (l == 0) ? BNAT : M4;
        int gW1 = (l == 0) ? gSm : gBig;
        // x = feat @ W1 + b1
        mmaGemmPS<128,0><<<gW1, 256, psSmem128>>>(feah, feal,
            WH + (size_t)(l*3+0)*DC*DC, WL + (size_t)(l*3+0)*DC*DC,
            xw4, mW1, b1 + l*DC, BNAT, nullptr, nullptr, nullptr);
        tabK2<<<NQ/QB, DC, tabSmem>>>(Wf1, bf1, Wf2, bf2, centers, gammaA, l);
        if (l == 0) aggV<true><<<dim3(NATC/4, BC), 128>>>(idx_j);
        else        aggV<false><<<dim3(NATC/4, BC), 128>>>(idx_j);
        // W2 primal rows: t3 = ssp(y@W2 + b2); sig stored
        mmaGemmPS<128,1><<<gSm, 256, psSmem128>>>(y4h, y4l,
            WH + (size_t)(l*3+1)*DC*DC, WL + (size_t)(l*3+1)*DC*DC,
            nullptr, BNAT, b2 + l*DC, 0, nullptr, t3h, t3l);
        // W2 tangent rows: t3dot = (ydot@W2) * sig
        mmaGemmPS<128,2><<<gT, 256, psSmem128>>>(y4h + TB, y4l + TB,
            WH + (size_t)(l*3+1)*DC*DC, WL + (size_t)(l*3+1)*DC*DC,
            nullptr, 3*BNAT, nullptr, 0, nullptr, t3h + TB, t3l + TB);
        // feat += s3 @ W3 + b3 (also emits feat bf16 hi/lo)
        mmaGemmPS<128,0><<<gBig, 256, psSmem128>>>(t3h, t3l,
            WH + (size_t)(l*3+2)*DC*DC, WL + (size_t)(l*3+2)*DC*DC,
            feat4, M4, b3 + l*DC, BNAT, feat4, feah, feal);
    }
    // pre = feat @ Wd + bd
    mmaGemmPS<64,0><<<gBig, 256, psSmem64>>>(feah, feal, WdH, WdL,
        h4, M4, bd, BNAT, nullptr, nullptr, nullptr);
    energyK<<<BC, 256>>>(We, out);
}

// round 17
// speedup vs baseline: 1.1037x; 1.1037x over previous
#include <cuda_runtime.h>
#include <cuda_bf16.h>
#include <math.h>
#include <stdint.h>

#define NATC 1024
#define DEGC 32
#define DC   128
#define RC   64
#define LC   3
#define BC   16
#define EC   (NATC*DEGC)      /* 32768 */
#define HDC  (DC/2)           /* 64 */
#define BNAT (BC*1024)        /* 16384 */
#define BE   ((size_t)BC*EC)  /* 524288 */
#define M4   (4*BNAT)         /* 65536 */
#define NQ   1024
#define QB   16
#define DMAXF 20.0f
#define LOG2C 0.69314718055994530942f

// ---------------- scratch (allocation-free: __device__ globals) ----------------
__device__ float g_xw4 [(size_t)4*BNAT*DC];
__device__ float g_feat4[(size_t)4*BNAT*DC];
__device__ float g_t34 [(size_t)4*BNAT*DC];
__device__ float g_h4  [(size_t)4*BNAT*HDC];
__device__ float g_d   [BE];
__device__ float g_ddot[(size_t)BE*3];
__device__ float          g_tabF [(size_t)NQ*DC];
__device__ __nv_bfloat16  g_tabDh[(size_t)NQ*DC];
__device__ float          g_tabDf[(size_t)NQ*DC];
__device__ int   g_sflag[EC];
__device__ int   g_reach0[NATC];
__device__ int   g_reach1[NATC];
// bf16 hi/lo operand planes (producer-packed)
__device__ __nv_bfloat16 g_feah[(size_t)4*BNAT*DC], g_feal[(size_t)4*BNAT*DC];
__device__ __nv_bfloat16 g_y4h [(size_t)4*BNAT*DC], g_y4l [(size_t)4*BNAT*DC];
__device__ __nv_bfloat16 g_t3h [(size_t)4*BNAT*DC], g_t3l [(size_t)4*BNAT*DC];
// pre-split transposed weights: [slot][n][k], slot = l*3 + {W1,W2,W3}; Wd separate
__device__ __nv_bfloat16 g_WH[(size_t)9*DC*DC], g_WL[(size_t)9*DC*DC];
__device__ __nv_bfloat16 g_WdH[(size_t)HDC*DC], g_WdL[(size_t)HDC*DC];

// ---------------- math helpers ----------------
__device__ __forceinline__ float sspf(float x) {
    return fmaxf(x, 0.f) + log1pf(expf(-fabsf(x))) - LOG2C;
}
__device__ __forceinline__ float sigf(float x) {
    return 1.f / (1.f + expf(-x));
}
__device__ __forceinline__ uint32_t smem_u32(const void* p) {
    uint32_t a;
    asm("{ .reg .u64 t; cvta.to.shared.u64 t, %1; cvt.u32.u64 %0, t; }" : "=r"(a) : "l"(p));
    return a;
}
__device__ __forceinline__ uint32_t pack_hi(float x0, float x1) {
    __nv_bfloat162 v; v.x = __float2bfloat16(x0); v.y = __float2bfloat16(x1);
    return *reinterpret_cast<uint32_t*>(&v);
}
__device__ __forceinline__ uint32_t pack_lo(float x0, float x1) {
    __nv_bfloat16 h0 = __float2bfloat16(x0), h1 = __float2bfloat16(x1);
    __nv_bfloat162 v;
    v.x = __float2bfloat16(x0 - __bfloat162float(h0));
    v.y = __float2bfloat16(x1 - __bfloat162float(h1));
    return *reinterpret_cast<uint32_t*>(&v);
}

// ---------------- prep ----------------
__global__ void prepBuildK(const int* __restrict__ idx_i, const int* __restrict__ idx_j) {
    int e = blockIdx.x * blockDim.x + threadIdx.x;
    if (e >= EC) return;
    g_sflag[e] = (idx_i[e] == 0 || idx_j[e] == 0) ? 1 : 0;
}

// reach0[i] = OR_e-in-row-i sflag[e]  (feat tangent support after layer 0)
__global__ void reach0K() {
    int i = blockIdx.x * blockDim.x + threadIdx.x;
    if (i >= NATC) return;
    int f = 0;
    #pragma unroll 8
    for (int eo = 0; eo < DEGC; eo++) f |= g_sflag[i*DEGC + eo];
    g_reach0[i] = f;
}
// reach1[i] = reach0[i] OR_e (sflag[e] | reach0[idx_j[e]])
__global__ void reach1K(const int* __restrict__ idx_j) {
    int i = blockIdx.x * blockDim.x + threadIdx.x;
    if (i >= NATC) return;
    int f = g_reach0[i];
    for (int eo = 0; eo < DEGC; eo++) {
        int e = i*DEGC + eo;
        f |= g_sflag[e] | g_reach0[idx_j[e]];
    }
    g_reach1[i] = f;
}

__global__ void initK(const float* __restrict__ emb, const int* __restrict__ types) {
    int gid = blockIdx.x * blockDim.x + threadIdx.x;
    if (gid >= BNAT * DC) return;
    int bn = gid / DC;
    int d  = gid - bn * DC;
    int ty = types[bn];
    const size_t TB = (size_t)BNAT * DC;
    float v = emb[(size_t)ty * DC + d];
    g_feat4[gid]        = v;
    g_feat4[TB + gid]   = 0.f;
    g_feat4[2*TB + gid] = 0.f;
    g_feat4[3*TB + gid] = 0.f;
    __nv_bfloat16 h = __float2bfloat16(v);
    __nv_bfloat16 l = __float2bfloat16(v - __bfloat162float(h));
    __nv_bfloat16 z = __float2bfloat16(0.f);
    g_feah[gid] = h; g_feal[gid] = l;
    g_feah[TB+gid] = z; g_feal[TB+gid] = z;
    g_feah[2*TB+gid] = z; g_feal[2*TB+gid] = z;
    g_feah[3*TB+gid] = z; g_feal[3*TB+gid] = z;
}

__global__ void distK(const float* __restrict__ pos,
                      const int* __restrict__ idx_i, const int* __restrict__ idx_j) {
    int gid = blockIdx.x * blockDim.x + threadIdx.x;
    if (gid >= (int)BE) return;
    int b = gid / EC, e = gid - b * EC;
    int i = idx_i[e], j = idx_j[e];
    const float* pi = pos + ((size_t)b * NATC + i) * 3;
    const float* pj = pos + ((size_t)b * NATC + j) * 3;
    float dx = pi[0]-pj[0], dy = pi[1]-pj[1], dz = pi[2]-pj[2];
    float dv = sqrtf(dx*dx + dy*dy + dz*dz + 1e-8f);
    g_d[gid] = dv;
    float c = (float)((i == 0) - (j == 0));
    float inv = c / dv;
    g_ddot[(size_t)gid*3 + 0] = dx * inv;
    g_ddot[(size_t)gid*3 + 1] = dy * inv;
    g_ddot[(size_t)gid*3 + 2] = dz * inv;
}

// ---------------- pre-split all weights (transposed [n][k], bf16 hi/lo), 4 chunks/matrix ----
__global__ void packWK(const float* __restrict__ W1, const float* __restrict__ W2,
                       const float* __restrict__ W3, const float* __restrict__ Wd) {
    int bid = blockIdx.x, tid = threadIdx.x;
    int mat = bid >> 2, part = bid & 3;
    if (mat < 9) {
        int l = mat / 3, w = mat % 3;
        const float* src = (w == 0 ? W1 : (w == 1 ? W2 : W3)) + (size_t)l*DC*DC;
        __nv_bfloat16* dh = g_WH + (size_t)mat*DC*DC;
        __nv_bfloat16* dl = g_WL + (size_t)mat*DC*DC;
        int n0 = part * (DC*DC/4), n1 = n0 + DC*DC/4;
        for (int i = n0 + tid; i < n1; i += 256) {
            int n = i >> 7, k = i & 127;
            float x = src[(size_t)k*DC + n];
            __nv_bfloat16 h = __float2bfloat16(x);
            dh[i] = h;
            dl[i] = __float2bfloat16(x - __bfloat162float(h));
        }
    } else {
        int n0 = part * (HDC*DC/4), n1 = n0 + HDC*DC/4;
        for (int i = n0 + tid; i < n1; i += 256) {
            int n = i >> 7, k = i & 127;
            float x = Wd[(size_t)k*HDC + n];
            __nv_bfloat16 h = __float2bfloat16(x);
            g_WdH[i] = h;
            g_WdL[i] = __float2bfloat16(x - __bfloat162float(h));
        }
    }
}

// ------ per-layer edge-MLP lookup table (weights cached in dynamic smem) ------
__global__ void tabK2(const float* __restrict__ Wf1, const float* __restrict__ bf1,
                      const float* __restrict__ Wf2, const float* __restrict__ bf2,
                      const float* __restrict__ centers, const float* __restrict__ gammaA, int l) {
    extern __shared__ float sw[];
    float* w1s = sw;
    float* w2s = sw + RC*DC;
    __shared__ float rbf[RC], drb[RC], s1[DC], ds1[DC];
    int t = threadIdx.x;
    for (int idx = t; idx < RC*DC; idx += DC) w1s[idx] = Wf1[(size_t)l*RC*DC + idx];
    for (int idx = t; idx < DC*DC; idx += DC) w2s[idx] = Wf2[(size_t)l*DC*DC + idx];
    float b1v = bf1[l*DC + t];
    float b2v = bf2[l*DC + t];
    float gm = 0.f, cc = 0.f;
    if (t < RC) { gm = gammaA[l*RC + t]; cc = centers[l*RC + t]; }
    __syncthreads();

    const float hh = DMAXF / (float)(NQ - 1);
    for (int qi = 0; qi < QB; qi++) {
        int q = blockIdx.x * QB + qi;
        float dq = q * hh;
        if (t < RC) {
            float diff = dq - cc;
            float r = expf(-gm * diff * diff);
            rbf[t] = r;
            drb[t] = -2.f * gm * diff * r;
        }
        __syncthreads();
        float t1 = b1v, dt1 = 0.f;
        #pragma unroll 8
        for (int r = 0; r < RC; r++) {
            float w = w1s[r * DC + t];
            t1  += rbf[r] * w;
            dt1 += drb[r] * w;
        }
        s1[t]  = sspf(t1);
        ds1[t] = sigf(t1) * dt1;
        __syncthreads();
        float t2 = b2v, dt2 = 0.f;
        #pragma unroll 8
        for (int k = 0; k < DC; k++) {
            float w = w2s[k * DC + t];
            t2  += s1[k] * w;
            dt2 += ds1[k] * w;
        }
        float fval = sspf(t2);
        float fder = sigf(t2) * dt2;
        g_tabF [(size_t)q*DC + t] = fval;
        g_tabDh[(size_t)q*DC + t] = __float2bfloat16(hh * fder);
        g_tabDf[(size_t)q*DC + t] = fder;
        __syncthreads();
    }
}

// ---------------- GEMM helpers ----------------
#define PADK 136
#define BPL (128 * PADK * 2)      /* 34816 B: one 128-row bf16 plane */

__device__ __forceinline__ void mma16816(float* c, uint32_t a0, uint32_t a1, uint32_t a2, uint32_t a3,
                                         uint32_t b0, uint32_t b1) {
    asm volatile(
        "mma.sync.aligned.m16n8k16.row.col.f32.bf16.bf16.f32 "
        "{%0,%1,%2,%3}, {%4,%5,%6,%7}, {%8,%9}, {%0,%1,%2,%3};"
        : "+f"(c[0]), "+f"(c[1]), "+f"(c[2]), "+f"(c[3])
        : "r"(a0), "r"(a1), "r"(a2), "r"(a3), "r"(b0), "r"(b1));
}
#define LDSM4(r0, r1, r2, r3, addr) \
    asm volatile("ldmatrix.sync.aligned.m8n8.x4.shared.b16 {%0,%1,%2,%3}, [%4];" \
        : "=r"(r0), "=r"(r1), "=r"(r2), "=r"(r3) : "r"(addr))
#define CP16(sa, ga) \
    asm volatile("cp.async.cg.shared.global [%0], [%1], 16;" :: "r"(sa), "l"(ga))
#define CPCOMMIT() asm volatile("cp.async.commit_group;" ::: "memory")
#define CPWAIT(n)  asm volatile("cp.async.wait_group %0;" :: "n"(n) : "memory")

// ---------------- persistent GEMM, cp.async double-buffered A tiles ----------------
template<int NN>
__global__ void __launch_bounds__(256) mmaGemmPS(
    const __nv_bfloat16* __restrict__ Ahg, const __nv_bfloat16* __restrict__ Alg,
    const __nv_bfloat16* __restrict__ Whg, const __nv_bfloat16* __restrict__ Wlg,
    float* __restrict__ C, int M,
    const float* __restrict__ bias, int biasRows, const float* __restrict__ res,
    __nv_bfloat16* __restrict__ Chg, __nv_bfloat16* __restrict__ Clg)
{
    extern __shared__ char sm[];
    const int tid = threadIdx.x;
    const int nT = M >> 7;
    if (blockIdx.x >= nT) return;
    constexpr uint32_t WBYTES = (uint32_t)NN * PADK * 2;
    const uint32_t smemU = smem_u32(sm);
    const uint32_t aBase = 2u * WBYTES;

    {
        #pragma unroll
        for (int it = 0; it < NN*16/256; it++) {
            int idx = it * 256 + tid;
            int n = idx >> 4, kq = idx & 15;
            uint32_t off = (uint32_t)n * (PADK*2) + kq * 16;
            CP16(smemU + off,           (const char*)Whg + idx*16);
            CP16(smemU + WBYTES + off,  (const char*)Wlg + idx*16);
        }
    }
    {
        int t0 = blockIdx.x;
        #pragma unroll
        for (int it = 0; it < 8; it++) {
            int idx = it * 256 + tid;
            int row = idx >> 4, kq = idx & 15;
            uint32_t off = aBase + (uint32_t)row * (PADK*2) + kq * 16;
            CP16(smemU + off,       (const char*)(Ahg + ((size_t)t0*128 + row) * DC) + kq*16);
            CP16(smemU + BPL + off, (const char*)(Alg + ((size_t)t0*128 + row) * DC) + kq*16);
        }
    }
    CPCOMMIT();

    const int wid = tid >> 5, lane = tid & 31;
    const int wm = wid & 3, wn = wid >> 2;
    const int g0 = (lane >> 3) & 1, g1 = (lane >> 4) & 1, r8 = lane & 7;
    const int lr = lane >> 2, lc = lane & 3;
    constexpr int NT = NN / 16;

    const uint32_t aOff = 2u * ((uint32_t)(wm*32 + g0*8 + r8) * PADK + g1*8);
    const uint32_t bAddr0 = smemU + 2u * ((uint32_t)(wn*(NN/2) + g1*8 + r8) * PADK + g0*8);

    int cb = 0;
    for (int t = blockIdx.x; t < nT; t += gridDim.x) {
        const int tn = t + gridDim.x;
        const bool more = tn < nT;
        if (more) {
            uint32_t nb = aBase + (uint32_t)(cb ^ 1) * (2*BPL);
            #pragma unroll
            for (int it = 0; it < 8; it++) {
                int idx = it * 256 + tid;
                int row = idx >> 4, kq = idx & 15;
                uint32_t off = nb + (uint32_t)row * (PADK*2) + kq * 16;
                CP16(smemU + off,       (const char*)(Ahg + ((size_t)tn*128 + row) * DC) + kq*16);
                CP16(smemU + BPL + off, (const char*)(Alg + ((size_t)tn*128 + row) * DC) + kq*16);
            }
            CPCOMMIT();
            CPWAIT(1);
        } else {
            CPWAIT(0);
        }
        __syncthreads();

        float acc[2][NT][4];
        #pragma unroll
        for (int mt = 0; mt < 2; mt++)
            #pragma unroll
            for (int nt = 0; nt < NT; nt++)
                #pragma unroll
                for (int q = 0; q < 4; q++) acc[mt][nt][q] = 0.f;

        const uint32_t aAddr0 = smemU + aBase + (uint32_t)cb * (2*BPL) + aOff;
        #pragma unroll
        for (int pass = 0; pass < 3; pass++) {
            const uint32_t aP = aAddr0 + ((pass == 1) ? (uint32_t)BPL : 0u);
            const uint32_t bP = bAddr0 + ((pass == 2) ? WBYTES : 0u);
            #pragma unroll
            for (int ks = 0; ks < 8; ks++) {
                uint32_t a[8];
                LDSM4(a[0], a[1], a[2], a[3], aP + ks*32);
                LDSM4(a[4], a[5], a[6], a[7], aP + 16u*2u*PADK + ks*32);
                #pragma unroll
                for (int p = 0; p < NT/2; p++) {
                    uint32_t bfr[4];
                    LDSM4(bfr[0], bfr[1], bfr[2], bfr[3], bP + (uint32_t)(p*16*2*PADK) + ks*32);
                    mma16816(acc[0][2*p],   a[0], a[1], a[2], a[3], bfr[0], bfr[1]);
                    mma16816(acc[1][2*p],   a[4], a[5], a[6], a[7], bfr[0], bfr[1]);
                    mma16816(acc[0][2*p+1], a[0], a[1], a[2], a[3], bfr[2], bfr[3]);
                    mma16816(acc[1][2*p+1], a[4], a[5], a[6], a[7], bfr[2], bfr[3]);
                }
            }
        }
        __syncthreads();

        const int m0 = t * 128;
        const int arow0 = wm * 32 + lr;
        #pragma unroll
        for (int mt = 0; mt < 2; mt++) {
            int r0 = m0 + arow0 + mt * 16;
            int r1 = r0 + 8;
            bool ub0 = (bias != nullptr) && (r0 < biasRows);
            bool ub1 = (bias != nullptr) && (r1 < biasRows);
            #pragma unroll
            for (int nt = 0; nt < NT; nt++) {
                int col = wn * (NN/2) + nt * 8 + lc * 2;
                float2 v0 = make_float2(acc[mt][nt][0], acc[mt][nt][1]);
                float2 v1 = make_float2(acc[mt][nt][2], acc[mt][nt][3]);
                if (ub0) { v0.x += bias[col]; v0.y += bias[col+1]; }
                if (ub1) { v1.x += bias[col]; v1.y += bias[col+1]; }
                if (res) {
                    float2 r0v = *reinterpret_cast<const float2*>(res + (size_t)r0 * NN + col);
                    float2 r1v = *reinterpret_cast<const float2*>(res + (size_t)r1 * NN + col);
                    v0.x += r0v.x; v0.y += r0v.y;
                    v1.x += r1v.x; v1.y += r1v.y;
                }
                *reinterpret_cast<float2*>(C + (size_t)r0 * NN + col) = v0;
                *reinterpret_cast<float2*>(C + (size_t)r1 * NN + col) = v1;
                if (Chg) {
                    *reinterpret_cast<uint32_t*>(Chg + (size_t)r0 * NN + col) = pack_hi(v0.x, v0.y);
                    *reinterpret_cast<uint32_t*>(Clg + (size_t)r0 * NN + col) = pack_lo(v0.x, v0.y);
                    *reinterpret_cast<uint32_t*>(Chg + (size_t)r1 * NN + col) = pack_hi(v1.x, v1.y);
                    *reinterpret_cast<uint32_t*>(Clg + (size_t)r1 * NN + col) = pack_lo(v1.x, v1.y);
                }
            }
        }
        cb ^= 1;
    }
}

// -------- vectorized agg with structural tangent-sparsity skip --------
template<bool LIGHT>
__global__ void __launch_bounds__(128) aggV(const int* __restrict__ idx_j,
                                            const int* __restrict__ reach) {
    const int b = blockIdx.y;
    const int warp = threadIdx.x >> 5, lane = threadIdx.x & 31;
    const int i = blockIdx.x * 4 + warp;
    const size_t TBq = ((size_t)BNAT * DC) >> 2;
    const float invh = (float)(NQ - 1) / DMAXF;

    __shared__ float sd[128], sdx[128], sdy[128], sdz[128];
    __shared__ int sj[128], sf[128];
    {
        int tid = threadIdx.x;
        int e = blockIdx.x * 128 + tid;
        sd[tid] = g_d[(size_t)b*EC + e];
        int j = idx_j[e];
        sj[tid] = j;
        // bit 0: special edge; bit 1: tangent x nonzero (reach)
        sf[tid] = g_sflag[e] | ((!LIGHT && reach[j]) ? 2 : 0);
        size_t db = ((size_t)b*EC + e) * 3;
        sdx[tid] = g_ddot[db + 0];
        sdy[tid] = g_ddot[db + 1];
        sdz[tid] = g_ddot[db + 2];
    }
    __syncthreads();

    const float4* xp = reinterpret_cast<const float4*>(g_xw4);
    const float4* tF = reinterpret_cast<const float4*>(g_tabF);
    const float4* tD = reinterpret_cast<const float4*>(g_tabDf);
    const uint2*  tH = reinterpret_cast<const uint2*>(g_tabDh);

    float4 y  = make_float4(0.f,0.f,0.f,0.f);
    float4 ya = y, yb_ = y, yc = y;
    const int e0 = warp * 32;

    #pragma unroll 4
    for (int eo = 0; eo < DEGC; eo++) {
        int ee = e0 + eo;
        float dv = sd[ee];
        float u = fminf(dv * invh, (float)(NQ - 1));
        int q = (int)u;
        if (q > NQ - 2) q = NQ - 2;
        float w = u - (float)q;
        float w2 = w*w, w3 = w2*w;
        float h00 = 2.f*w3 - 3.f*w2 + 1.f;
        float h01 = 1.f - h00;
        float h10 = w3 - 2.f*w2 + w;
        float h11 = w3 - w2;

        int ti0 = q * 32 + lane, ti1 = ti0 + 32;
        float4 f0 = tF[ti0], f1 = tF[ti1];
        uint2 hu0 = tH[ti0], hu1 = tH[ti1];
        float2 d0lo = __bfloat1622float2(*reinterpret_cast<const __nv_bfloat162*>(&hu0.x));
        float2 d0hi = __bfloat1622float2(*reinterpret_cast<const __nv_bfloat162*>(&hu0.y));
        float2 d1lo = __bfloat1622float2(*reinterpret_cast<const __nv_bfloat162*>(&hu1.x));
        float2 d1hi = __bfloat1622float2(*reinterpret_cast<const __nv_bfloat162*>(&hu1.y));

        float4 fv;
        fv.x = h00*f0.x + h01*f1.x + h10*d0lo.x + h11*d1lo.x;
        fv.y = h00*f0.y + h01*f1.y + h10*d0lo.y + h11*d1lo.y;
        fv.z = h00*f0.z + h01*f1.z + h10*d0hi.x + h11*d1hi.x;
        fv.w = h00*f0.w + h01*f1.w + h10*d0hi.y + h11*d1hi.y;

        int j = sj[ee];
        int flags = sf[ee];
        size_t xb = (((size_t)b*NATC + j) << 5) + lane;
        float4 xv = xp[xb];
        y.x += xv.x*fv.x; y.y += xv.y*fv.y; y.z += xv.z*fv.z; y.w += xv.w*fv.w;
        if (!LIGHT && (flags & 2)) {     // xdot[j] structurally nonzero
            float4 x0 = xp[TBq + xb];
            float4 x1 = xp[2*TBq + xb];
            float4 x2 = xp[3*TBq + xb];
            ya.x += x0.x*fv.x; ya.y += x0.y*fv.y; ya.z += x0.z*fv.z; ya.w += x0.w*fv.w;
            yb_.x += x1.x*fv.x; yb_.y += x1.y*fv.y; yb_.z += x1.z*fv.z; yb_.w += x1.w*fv.w;
            yc.x += x2.x*fv.x; yc.y += x2.y*fv.y; yc.z += x2.z*fv.z; yc.w += x2.w*fv.w;
        }

        if (flags & 1) {
            float4 g0v = tD[ti0], g1v = tD[ti1];
            float dcom = 6.f * (w2 - w) * invh;
            float c0 = 3.f*w2 - 4.f*w + 1.f;
            float c1 = 3.f*w2 - 2.f*w;
            float4 F;
            F.x = dcom*(f0.x - f1.x) + c0*g0v.x + c1*g1v.x;
            F.y = dcom*(f0.y - f1.y) + c0*g0v.y + c1*g1v.y;
            F.z = dcom*(f0.z - f1.z) + c0*g0v.z + c1*g1v.z;
            F.w = dcom*(f0.w - f1.w) + c0*g0v.w + c1*g1v.w;
            float ax = sdx[ee], ay = sdy[ee], az = sdz[ee];
            float4 xF;
            xF.x = xv.x*F.x; xF.y = xv.y*F.y; xF.z = xv.z*F.z; xF.w = xv.w*F.w;
            ya.x += ax*xF.x; ya.y += ax*xF.y; ya.z += ax*xF.z; ya.w += ax*xF.w;
            yb_.x += ay*xF.x; yb_.y += ay*xF.y; yb_.z += ay*xF.z; yb_.w += ay*xF.w;
            yc.x += az*xF.x; yc.y += az*xF.y; yc.z += az*xF.z; yc.w += az*xF.w;
        }
    }

    size_t bn = (size_t)b*NATC + i;
    int co = lane * 4;
    #pragma unroll
    for (int c = 0; c < 4; c++) {
        float4 v = (c == 0) ? y : (c == 1) ? ya : (c == 2) ? yb_ : yc;
        size_t base = (bn + (size_t)c * BNAT) * DC + co;
        *reinterpret_cast<uint2*>(g_y4h + base) = make_uint2(pack_hi(v.x, v.y), pack_hi(v.z, v.w));
        *reinterpret_cast<uint2*>(g_y4l + base) = make_uint2(pack_lo(v.x, v.y), pack_lo(v.z, v.w));
    }
}

// -------- ssp primal / sigmoid-mask tangents; emit bf16 hi/lo t34 --------
__global__ void sspT2K() {
    int gid = blockIdx.x * 256 + threadIdx.x;
    const size_t TBq = ((size_t)BNAT * DC) >> 2;
    const float4* t = reinterpret_cast<const float4*>(g_t34);
    float4 p = t[gid];
    float4 sg = make_float4(sigf(p.x), sigf(p.y), sigf(p.z), sigf(p.w));
    float4 o = make_float4(sspf(p.x), sspf(p.y), sspf(p.z), sspf(p.w));
    size_t base0 = (size_t)gid * 4;
    *reinterpret_cast<uint2*>(g_t3h + base0) = make_uint2(pack_hi(o.x, o.y), pack_hi(o.z, o.w));
    *reinterpret_cast<uint2*>(g_t3l + base0) = make_uint2(pack_lo(o.x, o.y), pack_lo(o.z, o.w));
    #pragma unroll
    for (int c = 1; c < 4; c++) {
        float4 v = t[(size_t)c * TBq + gid];
        v.x *= sg.x; v.y *= sg.y; v.z *= sg.z; v.w *= sg.w;
        size_t base = ((size_t)c * TBq + gid) * 4;
        *reinterpret_cast<uint2*>(g_t3h + base) = make_uint2(pack_hi(v.x, v.y), pack_hi(v.z, v.w));
        *reinterpret_cast<uint2*>(g_t3l + base) = make_uint2(pack_lo(v.x, v.y), pack_lo(v.z, v.w));
    }
}

// ---------------- final energy tangent reduction ----------------
__global__ void energyK(const float* __restrict__ We, float* __restrict__ out) {
    int b = blockIdx.x, tid = threadIdx.x;
    const size_t TH = (size_t)BNAT * HDC;
    float a0 = 0.f, a1 = 0.f, a2 = 0.f;
    for (int idx = tid; idx < NATC * HDC; idx += 256) {
        int k = idx & (HDC - 1);
        size_t base = (size_t)b * NATC * HDC + idx;
        float p = g_h4[base];
        float w = We[k] * sigf(p);
        a0 += w * g_h4[TH   + base];
        a1 += w * g_h4[2*TH + base];
        a2 += w * g_h4[3*TH + base];
    }
    __shared__ float r0[256], r1[256], r2[256];
    r0[tid] = a0; r1[tid] = a1; r2[tid] = a2;
    __syncthreads();
    for (int s = 128; s > 0; s >>= 1) {
        if (tid < s) { r0[tid] += r0[tid+s]; r1[tid] += r1[tid+s]; r2[tid] += r2[tid+s]; }
        __syncthreads();
    }
    if (tid == 0) {
        out[b*3 + 0] = -r0[0];
        out[b*3 + 1] = -r1[0];
        out[b*3 + 2] = -r2[0];
    }
}

// ---------------- host ----------------
extern "C" void kernel_launch(void* const* d_in, const int* in_sizes, int n_in,
                              void* d_out, int out_size) {
    const float* pos     = (const float*)d_in[0];
    const int*   types   = (const int*)  d_in[1];
    const int*   idx_i   = (const int*)  d_in[2];
    const int*   idx_j   = (const int*)  d_in[3];
    /* d_in[4] = seg_i (== idx_i, unused) */
    const float* emb     = (const float*)d_in[5];
    const float* W1      = (const float*)d_in[6];
    const float* b1      = (const float*)d_in[7];
    const float* Wf1     = (const float*)d_in[8];
    const float* bf1     = (const float*)d_in[9];
    const float* Wf2     = (const float*)d_in[10];
    const float* bf2     = (const float*)d_in[11];
    const float* W2      = (const float*)d_in[12];
    const float* b2      = (const float*)d_in[13];
    const float* W3      = (const float*)d_in[14];
    const float* b3      = (const float*)d_in[15];
    const float* centers = (const float*)d_in[16];
    const float* gammaA  = (const float*)d_in[17];
    const float* Wd      = (const float*)d_in[18];
    const float* bd      = (const float*)d_in[19];
    const float* We      = (const float*)d_in[20];
    float* out = (float*)d_out;

    float *feat4, *xw4, *t34, *h4;
    __nv_bfloat16 *feah, *feal, *y4h, *y4l, *t3h, *t3l, *WH, *WL, *WdH, *WdL;
    int *reach0, *reach1;
    cudaGetSymbolAddress((void**)&feat4, g_feat4);
    cudaGetSymbolAddress((void**)&xw4,  g_xw4);
    cudaGetSymbolAddress((void**)&t34,  g_t34);
    cudaGetSymbolAddress((void**)&h4,   g_h4);
    cudaGetSymbolAddress((void**)&feah, g_feah);
    cudaGetSymbolAddress((void**)&feal, g_feal);
    cudaGetSymbolAddress((void**)&y4h,  g_y4h);
    cudaGetSymbolAddress((void**)&y4l,  g_y4l);
    cudaGetSymbolAddress((void**)&t3h,  g_t3h);
    cudaGetSymbolAddress((void**)&t3l,  g_t3l);
    cudaGetSymbolAddress((void**)&WH,   g_WH);
    cudaGetSymbolAddress((void**)&WL,   g_WL);
    cudaGetSymbolAddress((void**)&WdH,  g_WdH);
    cudaGetSymbolAddress((void**)&WdL,  g_WdL);
    cudaGetSymbolAddress((void**)&reach0, g_reach0);
    cudaGetSymbolAddress((void**)&reach1, g_reach1);

    const int tabSmem = (RC*DC + DC*DC) * sizeof(float);               // 96 KB
    const int psSmem128 = 2*(128*PADK*2) + 4*BPL;                      // 204 KB
    const int psSmem64  = 2*(64*PADK*2)  + 4*BPL;                      // 170 KB
    cudaFuncSetAttribute(tabK2, cudaFuncAttributeMaxDynamicSharedMemorySize, tabSmem);
    cudaFuncSetAttribute(mmaGemmPS<128>, cudaFuncAttributeMaxDynamicSharedMemorySize, psSmem128);
    cudaFuncSetAttribute(mmaGemmPS<64>,  cudaFuncAttributeMaxDynamicSharedMemorySize, psSmem64);

    prepBuildK<<<EC/256, 256>>>(idx_i, idx_j);
    reach0K<<<NATC/256, 256>>>();
    reach1K<<<NATC/256, 256>>>(idx_j);
    initK<<<(BNAT*DC)/256, 256>>>(emb, types);
    distK<<<(int)(BE/256), 256>>>(pos, idx_i, idx_j);
    packWK<<<40, 256>>>(W1, W2, W3, Wd);

    const int gBig = 152 < M4/128 ? 152 : M4/128;
    const int gSm  = 152 < BNAT/128 ? 152 : BNAT/128;

    for (int l = 0; l < LC; l++) {
        int mW1 = (l == 0) ? BNAT : M4;
        int gW1 = (l == 0) ? gSm : gBig;
        // x = feat @ W1 + b1
        mmaGemmPS<128><<<gW1, 256, psSmem128>>>(feah, feal,
            WH + (size_t)(l*3+0)*DC*DC, WL + (size_t)(l*3+0)*DC*DC,
            xw4, mW1, b1 + l*DC, BNAT, nullptr, nullptr, nullptr);
        tabK2<<<NQ/QB, DC, tabSmem>>>(Wf1, bf1, Wf2, bf2, centers, gammaA, l);
        if (l == 0)      aggV<true><<<dim3(NATC/4, BC), 128>>>(idx_j, reach0);
        else if (l == 1) aggV<false><<<dim3(NATC/4, BC), 128>>>(idx_j, reach0);
        else             aggV<false><<<dim3(NATC/4, BC), 128>>>(idx_j, reach1);
        // t3 = y @ W2 + b2
        mmaGemmPS<128><<<gBig, 256, psSmem128>>>(y4h, y4l,
            WH + (size_t)(l*3+1)*DC*DC, WL + (size_t)(l*3+1)*DC*DC,
            t34, M4, b2 + l*DC, BNAT, nullptr, nullptr, nullptr);
        // ssp/sigmoid -> bf16 hi/lo
        sspT2K<<<(BNAT*DC/4)/256, 256>>>();
        // feat += s3 @ W3 + b3 (also emits feat bf16 hi/lo)
        mmaGemmPS<128><<<gBig, 256, psSmem128>>>(t3h, t3l,
            WH + (size_t)(l*3+2)*DC*DC, WL + (size_t)(l*3+2)*DC*DC,
            feat4, M4, b3 + l*DC, BNAT, feat4, feah, feal);
    }
    // pre = feat @ Wd + bd
    mmaGemmPS<64><<<gBig, 256, psSmem64>>>(feah, feal, WdH, WdL,
        h4, M4, bd, BNAT, nullptr, nullptr, nullptr);
    energyK<<<BC, 256>>>(We, out);
}